// round 8
// baseline (speedup 1.0000x reference)
#include <cuda_runtime.h>
#include <cstdint>

#define NB   64
#define LSEQ 1024
#define DIMK 640
#define NIN  256
#define NOUT 1024

// scratch: 0=Qa(scaled,tf32), 1=Ka(tf32), 2=Qb(scaled,tf32), 3=Kb(tf32)
__device__ float g_proj[4][NB * LSEQ * NIN];          // 256 MB
__device__ float g_exp[2ull * NB * LSEQ * LSEQ];      // 512 MB
__device__ float g_recip[2 * NB * LSEQ];
__device__ float g_colsum[2 * NB * LSEQ];
__device__ float g_t[2 * NB * DIMK];

__device__ __forceinline__ float f2tf32(float x) {
    uint32_t u;
    asm("cvt.rna.tf32.f32 %0, %1;" : "=r"(u) : "f"(x));
    return __uint_as_float(u);
}

__device__ __forceinline__ void mma_tf32(float c[4], const uint32_t a[4],
                                         uint32_t b0, uint32_t b1) {
    asm volatile(
        "mma.sync.aligned.m16n8k8.row.col.f32.tf32.tf32.f32 "
        "{%0,%1,%2,%3}, {%4,%5,%6,%7}, {%8,%9}, {%0,%1,%2,%3};"
        : "+f"(c[0]), "+f"(c[1]), "+f"(c[2]), "+f"(c[3])
        : "r"(a[0]), "r"(a[1]), "r"(a[2]), "r"(a[3]), "r"(b0), "r"(b1));
}

#define CP16(dst_u32, src_ptr) \
    asm volatile("cp.async.cg.shared.global [%0], [%1], 16;" :: "r"(dst_u32), "l"(src_ptr))
#define CP_COMMIT() asm volatile("cp.async.commit_group;")
#define CP_WAIT(n)  asm volatile("cp.async.wait_group %0;" :: "n"(n))

__global__ __launch_bounds__(256) void init_kernel() {
    int i = blockIdx.x * 256 + threadIdx.x;
    if (i < 2 * NB * LSEQ) g_colsum[i] = 0.f;
    if (i < 2 * NB * DIMK) g_t[i] = 0.f;
}

// no-op: shifts the ncu capture slot (launch idx 3) onto attn_kernel
__global__ void dummy_kernel() {}

// ---------------------------------------------------------------------------
// Projection: C[65536,256] = X[65536,640] @ W[640,256]; stores f2tf32((C+b)*scl).
// CTA tile 128x256, 8 warps 2m x 4n (warp 64x64). cp.async 3-stage, K-chunk 16.
// Inputs consumed raw (HW tf32 truncation = uniform (1-2^-11) shrink, softmax-safe).
// smem: As 3*128*20 + Bs 3*16*264 = 20352 floats = 81408 B.
// ---------------------------------------------------------------------------
__global__ __launch_bounds__(256) void proj_kernel(
    const float* __restrict__ a_pad, const float* __restrict__ b_pad,
    const float* __restrict__ Wq, const float* __restrict__ bq,
    const float* __restrict__ Wk, const float* __restrict__ bk,
    const int* __restrict__ len_a, const int* __restrict__ len_b) {
    extern __shared__ float sm[];
    float* As = sm;          // 3*2560
    float* Bs = sm + 7680;   // 3*4224

    int z = blockIdx.z;
    int m0 = blockIdx.x * 128;
    int batch = m0 >> 10, local = m0 & 1023;
    int len = ((z < 2) ? len_a : len_b)[batch];
    if (local >= len) return;

    const float* X    = (z < 2) ? a_pad : b_pad;
    const float* W    = (z & 1) ? Wk : Wq;
    const float* bias = (z & 1) ? bk : bq;
    float scl         = (z & 1) ? 1.0f : 0.0625f;
    float* dst        = g_proj[z];

    int tid = threadIdx.x;
    int w = tid >> 5, lane = tid & 31;
    int wm = w & 1, wn = w >> 1;
    int g = lane >> 2, t4 = lane & 3;

    uint32_t smb = (uint32_t)__cvta_generic_to_shared(sm);

    // 16B chunk coords: A 2/thread (128x16), B 4/thread (16x256)
    int ar[2], ac[2], br[4], bc[4];
#pragma unroll
    for (int i = 0; i < 2; i++) {
        int idx = tid + 256 * i;
        ar[i] = idx >> 2;  ac[i] = (idx & 3) * 4;
    }
#pragma unroll
    for (int i = 0; i < 4; i++) {
        int idx = tid + 256 * i;
        br[i] = idx >> 6;  bc[i] = (idx & 63) * 4;
    }

    float acc[4][8][4] = {};
    const int NS = DIMK / 16;  // 40

#pragma unroll
    for (int p = 0; p < 2; p++) {  // prologue: stages 0,1
#pragma unroll
        for (int i = 0; i < 2; i++)
            CP16(smb + (p * 2560 + ar[i] * 20 + ac[i]) * 4,
                 X + (size_t)(m0 + ar[i]) * DIMK + p * 16 + ac[i]);
#pragma unroll
        for (int i = 0; i < 4; i++)
            CP16(smb + (7680 + p * 4224 + br[i] * 264 + bc[i]) * 4,
                 W + (size_t)(p * 16 + br[i]) * NIN + bc[i]);
        CP_COMMIT();
    }

    for (int s = 0; s < NS; s++) {
        if (s + 2 <= NS) { CP_WAIT(1); } else { CP_WAIT(0); }
        __syncthreads();
        if (s + 2 < NS) {
            int pb = (s + 2) % 3;
#pragma unroll
            for (int i = 0; i < 2; i++)
                CP16(smb + (pb * 2560 + ar[i] * 20 + ac[i]) * 4,
                     X + (size_t)(m0 + ar[i]) * DIMK + (s + 2) * 16 + ac[i]);
#pragma unroll
            for (int i = 0; i < 4; i++)
                CP16(smb + (7680 + pb * 4224 + br[i] * 264 + bc[i]) * 4,
                     W + (size_t)((s + 2) * 16 + br[i]) * NIN + bc[i]);
            CP_COMMIT();
        }
        const float* Ab = As + (s % 3) * 2560;
        const float* Bb = Bs + (s % 3) * 4224;
#pragma unroll
        for (int ks = 0; ks < 2; ks++) {
            int kb = ks * 8;
            uint32_t af[4][4];
#pragma unroll
            for (int i = 0; i < 4; i++) {
                int r = wm * 64 + i * 16 + g;
                af[i][0] = __float_as_uint(Ab[r * 20 + kb + t4]);
                af[i][1] = __float_as_uint(Ab[(r + 8) * 20 + kb + t4]);
                af[i][2] = __float_as_uint(Ab[r * 20 + kb + t4 + 4]);
                af[i][3] = __float_as_uint(Ab[(r + 8) * 20 + kb + t4 + 4]);
            }
#pragma unroll
            for (int j = 0; j < 8; j++) {
                int cb = wn * 64 + j * 8 + g;
                uint32_t b0 = __float_as_uint(Bb[(kb + t4) * 264 + cb]);
                uint32_t b1 = __float_as_uint(Bb[(kb + t4 + 4) * 264 + cb]);
#pragma unroll
                for (int i = 0; i < 4; i++) mma_tf32(acc[i][j], af[i], b0, b1);
            }
        }
    }

    // epilogue: RNA-round to tf32 so attn consumes clean pre-rounded bits
#pragma unroll
    for (int i = 0; i < 4; i++) {
        int r = m0 + wm * 64 + i * 16 + g;
#pragma unroll
        for (int j = 0; j < 8; j++) {
            int c = wn * 64 + j * 8 + t4 * 2;
            float bb0 = bias[c], bb1 = bias[c + 1];
            float2 v0 = make_float2(f2tf32((acc[i][j][0] + bb0) * scl),
                                    f2tf32((acc[i][j][1] + bb1) * scl));
            float2 v1 = make_float2(f2tf32((acc[i][j][2] + bb0) * scl),
                                    f2tf32((acc[i][j][3] + bb1) * scl));
            *(float2*)(dst + (size_t)r * NIN + c) = v0;
            *(float2*)(dst + (size_t)(r + 8) * NIN + c) = v1;
        }
    }
}

// ---------------------------------------------------------------------------
// Attention: S = Q @ K^T, E = exp(S) -> g_exp (streaming), rowsum -> g_recip.
// CTA: 128 q x 128 k, 8 warps 2m x 4n (warp 64x32), 2 CTAs/SM.
// cp.async 3-stage pipeline, K-chunk 16, inputs pre-rounded tf32.
// smem: 15488 floats = 61952 B.
// ---------------------------------------------------------------------------
__global__ __launch_bounds__(256, 2) void attn_kernel(
    const int* __restrict__ len_a, const int* __restrict__ len_b) {
    extern __shared__ float sm[];
    float* Qs = sm;             // 3*2560
    float* Ks = sm + 7680;      // 3*2560
    float* srow = sm + 15360;   // 128

    int side = blockIdx.z, batch = blockIdx.y, q0 = blockIdx.x * 128;
    int len_q = (side == 0) ? len_a[batch] : len_b[batch];
    int len_k = (side == 0) ? len_b[batch] : len_a[batch];
    if (q0 >= len_q) return;

    const float* Qg = g_proj[side == 0 ? 0 : 2] + (size_t)batch * LSEQ * NIN;
    const float* Kg = g_proj[side == 0 ? 3 : 1] + (size_t)batch * LSEQ * NIN;
    float* Eb = g_exp + (size_t)(side * NB + batch) * LSEQ * LSEQ;

    int tid = threadIdx.x;
    int w = tid >> 5, lane = tid & 31;
    int wm = w & 1, wn = w >> 1;
    int g = lane >> 2, t4 = lane & 3;

    uint32_t smb = (uint32_t)__cvta_generic_to_shared(sm);

    int qrow[2], qcol[2];
#pragma unroll
    for (int i = 0; i < 2; i++) {
        int c = tid + 256 * i;
        qrow[i] = c >> 2;  qcol[i] = (c & 3) * 4;
    }

    if (tid < 128) srow[tid] = 0.f;

    int nkt = (len_k + 127) >> 7;
    for (int kt = 0; kt < nkt; kt++) {
        int k0 = kt * 128;
        float acc[4][4][4] = {};
        const int NS = NIN / 16;  // 16

        __syncthreads();  // smem reuse fence (covers srow init on kt==0)

#pragma unroll
        for (int p = 0; p < 2; p++) {
#pragma unroll
            for (int i = 0; i < 2; i++) {
                CP16(smb + (p * 2560 + qrow[i] * 20 + qcol[i]) * 4,
                     Qg + (size_t)(q0 + qrow[i]) * NIN + p * 16 + qcol[i]);
                CP16(smb + (7680 + p * 2560 + qrow[i] * 20 + qcol[i]) * 4,
                     Kg + (size_t)(k0 + qrow[i]) * NIN + p * 16 + qcol[i]);
            }
            CP_COMMIT();
        }

        for (int s = 0; s < NS; s++) {
            if (s + 2 <= NS) { CP_WAIT(1); } else { CP_WAIT(0); }
            __syncthreads();
            if (s + 2 < NS) {
                int pb = (s + 2) % 3;
#pragma unroll
                for (int i = 0; i < 2; i++) {
                    CP16(smb + (pb * 2560 + qrow[i] * 20 + qcol[i]) * 4,
                         Qg + (size_t)(q0 + qrow[i]) * NIN + (s + 2) * 16 + qcol[i]);
                    CP16(smb + (7680 + pb * 2560 + qrow[i] * 20 + qcol[i]) * 4,
                         Kg + (size_t)(k0 + qrow[i]) * NIN + (s + 2) * 16 + qcol[i]);
                }
                CP_COMMIT();
            }
            const float* Qb = Qs + (s % 3) * 2560;
            const float* Kb = Ks + (s % 3) * 2560;
#pragma unroll
            for (int ks = 0; ks < 2; ks++) {
                int kb = ks * 8;
                uint32_t af[4][4];
#pragma unroll
                for (int i = 0; i < 4; i++) {
                    int r = wm * 64 + i * 16 + g;
                    af[i][0] = __float_as_uint(Qb[r * 20 + kb + t4]);
                    af[i][1] = __float_as_uint(Qb[(r + 8) * 20 + kb + t4]);
                    af[i][2] = __float_as_uint(Qb[r * 20 + kb + t4 + 4]);
                    af[i][3] = __float_as_uint(Qb[(r + 8) * 20 + kb + t4 + 4]);
                }
#pragma unroll
                for (int j = 0; j < 4; j++) {
                    int cb = wn * 32 + j * 8 + g;
                    uint32_t b0 = __float_as_uint(Kb[cb * 20 + kb + t4]);
                    uint32_t b1 = __float_as_uint(Kb[cb * 20 + kb + t4 + 4]);
#pragma unroll
                    for (int i = 0; i < 4; i++) mma_tf32(acc[i][j], af[i], b0, b1);
                }
            }
        }

#pragma unroll
        for (int i = 0; i < 4; i++) {
            int r = wm * 64 + i * 16 + g;
            float rs0 = 0.f, rs1 = 0.f;
#pragma unroll
            for (int j = 0; j < 4; j++) {
                int kc = k0 + wn * 32 + j * 8 + t4 * 2;
                float e00 = (kc < len_k) ? __expf(acc[i][j][0]) : 0.f;
                float e01 = (kc + 1 < len_k) ? __expf(acc[i][j][1]) : 0.f;
                float e10 = (kc < len_k) ? __expf(acc[i][j][2]) : 0.f;
                float e11 = (kc + 1 < len_k) ? __expf(acc[i][j][3]) : 0.f;
                __stcs((float2*)(Eb + (size_t)(q0 + r) * LSEQ + kc), make_float2(e00, e01));
                __stcs((float2*)(Eb + (size_t)(q0 + r + 8) * LSEQ + kc), make_float2(e10, e11));
                rs0 += e00 + e01;
                rs1 += e10 + e11;
            }
            rs0 += __shfl_xor_sync(~0u, rs0, 1); rs0 += __shfl_xor_sync(~0u, rs0, 2);
            rs1 += __shfl_xor_sync(~0u, rs1, 1); rs1 += __shfl_xor_sync(~0u, rs1, 2);
            if (t4 == 0) {
                atomicAdd(&srow[r], rs0);
                atomicAdd(&srow[r + 8], rs1);
            }
        }
    }
    __syncthreads();
    if (tid < 128)
        g_recip[(side * NB + batch) * LSEQ + q0 + tid] = 1.0f / srow[tid];
}

// colsum_k += sum_{q in chunk} E[q,k] * recip[q].  4-way q-split.
__global__ __launch_bounds__(256) void colsum_kernel(
    const int* __restrict__ len_a, const int* __restrict__ len_b) {
    int side = blockIdx.z, batch = blockIdx.y;
    int len_q = (side == 0) ? len_a[batch] : len_b[batch];
    int len_k = (side == 0) ? len_b[batch] : len_a[batch];
    int kc = blockIdx.x & 3, qc = blockIdx.x >> 2;
    int k = kc * 256 + threadIdx.x;
    int qlo = qc * 256;
    if (k >= len_k || qlo >= len_q) return;
    int qhi = min(qlo + 256, len_q);
    const float* E = g_exp + (size_t)(side * NB + batch) * LSEQ * LSEQ + k;
    const float* r = g_recip + (side * NB + batch) * LSEQ;
    float a0 = 0.f, a1 = 0.f, a2 = 0.f, a3 = 0.f;
    int q = qlo;
    for (; q + 16 <= qhi; q += 16) {
        float v[16];
#pragma unroll
        for (int i = 0; i < 16; i++) v[i] = __ldcs(E + (size_t)(q + i) * LSEQ);
#pragma unroll
        for (int i = 0; i < 4; i++) {
            a0 += v[i * 4 + 0] * r[q + i * 4 + 0];
            a1 += v[i * 4 + 1] * r[q + i * 4 + 1];
            a2 += v[i * 4 + 2] * r[q + i * 4 + 2];
            a3 += v[i * 4 + 3] * r[q + i * 4 + 3];
        }
    }
    for (; q < qhi; q++) a0 += __ldcs(E + (size_t)q * LSEQ) * r[q];
    atomicAdd(&g_colsum[(side * NB + batch) * LSEQ + k], (a0 + a1) + (a2 + a3));
}

// t[sb,:] += colsum_chunk @ pad.  8-way k split, unroll 8.
__global__ __launch_bounds__(640) void tvec_kernel(
    const float* __restrict__ a_pad, const float* __restrict__ b_pad,
    const int* __restrict__ len_a, const int* __restrict__ len_b) {
    int sb = blockIdx.y, side = sb >> 6, batch = sb & 63;
    int lk = (side == 0) ? len_b[batch] : len_a[batch];
    int k0 = blockIdx.x * 128;
    if (k0 >= lk) return;
    int k1 = min(k0 + 128, lk);
    const float* pad = ((side == 0) ? b_pad : a_pad) + (size_t)batch * LSEQ * DIMK;
    const float* cs = g_colsum + sb * LSEQ;
    int d = threadIdx.x;
    float a0 = 0.f, a1 = 0.f, a2 = 0.f, a3 = 0.f;
    int k = k0;
    for (; k + 8 <= k1; k += 8) {
        float v[8];
#pragma unroll
        for (int i = 0; i < 8; i++) v[i] = __ldcs(pad + (size_t)(k + i) * DIMK + d);
        a0 += cs[k] * v[0] + cs[k + 4] * v[4];
        a1 += cs[k + 1] * v[1] + cs[k + 5] * v[5];
        a2 += cs[k + 2] * v[2] + cs[k + 6] * v[6];
        a3 += cs[k + 3] * v[3] + cs[k + 7] * v[7];
    }
    for (; k < k1; k++) a0 += cs[k] * __ldcs(pad + (size_t)k * DIMK + d);
    atomicAdd(&g_t[sb * DIMK + d], (a0 + a1) + (a2 + a3));
}

// out[128,1024] = diag(1/len) * (t[128,640] @ Wv[640,1024]) + bv.
__global__ __launch_bounds__(256) void emb_kernel(
    const float* __restrict__ Wv, const float* __restrict__ bv,
    const int* __restrict__ len_a, const int* __restrict__ len_b,
    float* __restrict__ out) {
    __shared__ float ts[16][DIMK];
    int r0 = blockIdx.y * 16;
    int o = blockIdx.x * 256 + threadIdx.x;
    for (int i = threadIdx.x; i < 16 * DIMK; i += 256)
        ts[i / DIMK][i % DIMK] = g_t[(size_t)r0 * DIMK + i];
    __syncthreads();
    float acc[16] = {};
    for (int d = 0; d < DIMK; d++) {
        float wv = Wv[(size_t)d * NOUT + o];
#pragma unroll
        for (int r = 0; r < 16; r++) acc[r] += ts[r][d] * wv;
    }
    float bb = bv[o];
#pragma unroll
    for (int r = 0; r < 16; r++) {
        int sb = r0 + r;
        int side = sb >> 6, batch = sb & 63;
        float inv = 1.0f / (float)((side == 0 ? len_a : len_b)[batch]);
        out[(size_t)sb * NOUT + o] = acc[r] * inv + bb;
    }
}

extern "C" void kernel_launch(void* const* d_in, const int* in_sizes, int n_in,
                              void* d_out, int out_size) {
    const float* a_pad = (const float*)d_in[0];
    const float* b_pad = (const float*)d_in[1];
    const int*   len_a = (const int*)d_in[2];
    const int*   len_b = (const int*)d_in[3];
    const float* Wq = (const float*)d_in[4];
    const float* bq = (const float*)d_in[5];
    const float* Wk = (const float*)d_in[6];
    const float* bk = (const float*)d_in[7];
    const float* Wv = (const float*)d_in[8];
    const float* bv = (const float*)d_in[9];
    float* out = (float*)d_out;

    cudaFuncSetAttribute(proj_kernel, cudaFuncAttributeMaxDynamicSharedMemorySize, 81408);
    cudaFuncSetAttribute(attn_kernel, cudaFuncAttributeMaxDynamicSharedMemorySize, 61952);

    init_kernel<<<512, 256>>>();                                   // launch 0
    dummy_kernel<<<1, 32>>>();                                     // launch 1 (capture shim)
    dim3 gp(NB * LSEQ / 128, 1, 4);
    proj_kernel<<<gp, 256, 81408>>>(a_pad, b_pad, Wq, bq, Wk, bk, len_a, len_b);  // 2
    dim3 ga(LSEQ / 128, NB, 2);
    attn_kernel<<<ga, 256, 61952>>>(len_a, len_b);                 // launch 3 -> profiled
    dim3 gc(16, NB, 2);
    colsum_kernel<<<gc, 256>>>(len_a, len_b);
    dim3 gt(8, 2 * NB);
    tvec_kernel<<<gt, 640>>>(a_pad, b_pad, len_a, len_b);
    dim3 ge(4, 8);
    emb_kernel<<<ge, 256>>>(Wv, bv, len_a, len_b, out);
}

// round 9
// speedup vs baseline: 1.0268x; 1.0268x over previous
#include <cuda_runtime.h>
#include <cuda_fp16.h>
#include <cstdint>

#define NB   64
#define LSEQ 1024
#define DIMK 640
#define NIN  256
#define NOUT 1024

// scratch: 0=Qa(log2e-scaled,tf32), 1=Ka(tf32), 2=Qb, 3=Kb
__device__ float  g_proj[4][NB * LSEQ * NIN];          // 256 MB
__device__ __half g_exp[2ull * NB * LSEQ * LSEQ];      // 256 MB
__device__ float  g_recip[2 * NB * LSEQ];
__device__ float  g_colsum[2 * NB * LSEQ];
__device__ float  g_t[2 * NB * DIMK];

__device__ __forceinline__ float f2tf32(float x) {
    uint32_t u;
    asm("cvt.rna.tf32.f32 %0, %1;" : "=r"(u) : "f"(x));
    return __uint_as_float(u);
}

__device__ __forceinline__ void mma_tf32(float c[4], const uint32_t a[4],
                                         uint32_t b0, uint32_t b1) {
    asm volatile(
        "mma.sync.aligned.m16n8k8.row.col.f32.tf32.tf32.f32 "
        "{%0,%1,%2,%3}, {%4,%5,%6,%7}, {%8,%9}, {%0,%1,%2,%3};"
        : "+f"(c[0]), "+f"(c[1]), "+f"(c[2]), "+f"(c[3])
        : "r"(a[0]), "r"(a[1]), "r"(a[2]), "r"(a[3]), "r"(b0), "r"(b1));
}

#define CP16(dst_u32, src_ptr) \
    asm volatile("cp.async.cg.shared.global [%0], [%1], 16;" :: "r"(dst_u32), "l"(src_ptr))
#define CP_COMMIT() asm volatile("cp.async.commit_group;")
#define CP_WAIT(n)  asm volatile("cp.async.wait_group %0;" :: "n"(n))

__global__ __launch_bounds__(256) void init_kernel() {
    int i = blockIdx.x * 256 + threadIdx.x;
    if (i < 2 * NB * LSEQ) g_colsum[i] = 0.f;
    if (i < 2 * NB * DIMK) g_t[i] = 0.f;
}

// no-op: keeps attn_kernel in the ncu capture slot (launch idx 3)
__global__ void dummy_kernel() {}

// ---------------------------------------------------------------------------
// Projection: C[65536,256] = X[65536,640] @ W[640,256]; stores f2tf32((C+b)*scl).
// Q-side scl includes log2(e) so attention scores land in log2 domain.
// CTA tile 128x256, 8 warps 2m x 4n. cp.async 3-stage, K-chunk 16.
// ---------------------------------------------------------------------------
__global__ __launch_bounds__(256) void proj_kernel(
    const float* __restrict__ a_pad, const float* __restrict__ b_pad,
    const float* __restrict__ Wq, const float* __restrict__ bq,
    const float* __restrict__ Wk, const float* __restrict__ bk,
    const int* __restrict__ len_a, const int* __restrict__ len_b) {
    extern __shared__ float sm[];
    float* As = sm;          // 3*2560
    float* Bs = sm + 7680;   // 3*4224

    int z = blockIdx.z;
    int m0 = blockIdx.x * 128;
    int batch = m0 >> 10, local = m0 & 1023;
    int len = ((z < 2) ? len_a : len_b)[batch];
    if (local >= len) return;

    const float* X    = (z < 2) ? a_pad : b_pad;
    const float* W    = (z & 1) ? Wk : Wq;
    const float* bias = (z & 1) ? bk : bq;
    float scl         = (z & 1) ? 1.0f : 0.09016844005f;  // log2(e)/16
    float* dst        = g_proj[z];

    int tid = threadIdx.x;
    int w = tid >> 5, lane = tid & 31;
    int wm = w & 1, wn = w >> 1;
    int g = lane >> 2, t4 = lane & 3;

    uint32_t smb = (uint32_t)__cvta_generic_to_shared(sm);

    int ar[2], ac[2], br[4], bc[4];
#pragma unroll
    for (int i = 0; i < 2; i++) {
        int idx = tid + 256 * i;
        ar[i] = idx >> 2;  ac[i] = (idx & 3) * 4;
    }
#pragma unroll
    for (int i = 0; i < 4; i++) {
        int idx = tid + 256 * i;
        br[i] = idx >> 6;  bc[i] = (idx & 63) * 4;
    }

    float acc[4][8][4] = {};
    const int NS = DIMK / 16;  // 40

#pragma unroll
    for (int p = 0; p < 2; p++) {
#pragma unroll
        for (int i = 0; i < 2; i++)
            CP16(smb + (p * 2560 + ar[i] * 20 + ac[i]) * 4,
                 X + (size_t)(m0 + ar[i]) * DIMK + p * 16 + ac[i]);
#pragma unroll
        for (int i = 0; i < 4; i++)
            CP16(smb + (7680 + p * 4224 + br[i] * 264 + bc[i]) * 4,
                 W + (size_t)(p * 16 + br[i]) * NIN + bc[i]);
        CP_COMMIT();
    }

    for (int s = 0; s < NS; s++) {
        if (s + 2 <= NS) { CP_WAIT(1); } else { CP_WAIT(0); }
        __syncthreads();
        if (s + 2 < NS) {
            int pb = (s + 2) % 3;
#pragma unroll
            for (int i = 0; i < 2; i++)
                CP16(smb + (pb * 2560 + ar[i] * 20 + ac[i]) * 4,
                     X + (size_t)(m0 + ar[i]) * DIMK + (s + 2) * 16 + ac[i]);
#pragma unroll
            for (int i = 0; i < 4; i++)
                CP16(smb + (7680 + pb * 4224 + br[i] * 264 + bc[i]) * 4,
                     W + (size_t)((s + 2) * 16 + br[i]) * NIN + bc[i]);
            CP_COMMIT();
        }
        const float* Ab = As + (s % 3) * 2560;
        const float* Bb = Bs + (s % 3) * 4224;
#pragma unroll
        for (int ks = 0; ks < 2; ks++) {
            int kb = ks * 8;
            uint32_t af[4][4];
#pragma unroll
            for (int i = 0; i < 4; i++) {
                int r = wm * 64 + i * 16 + g;
                af[i][0] = __float_as_uint(Ab[r * 20 + kb + t4]);
                af[i][1] = __float_as_uint(Ab[(r + 8) * 20 + kb + t4]);
                af[i][2] = __float_as_uint(Ab[r * 20 + kb + t4 + 4]);
                af[i][3] = __float_as_uint(Ab[(r + 8) * 20 + kb + t4 + 4]);
            }
#pragma unroll
            for (int j = 0; j < 8; j++) {
                int cb = wn * 64 + j * 8 + g;
                uint32_t b0 = __float_as_uint(Bb[(kb + t4) * 264 + cb]);
                uint32_t b1 = __float_as_uint(Bb[(kb + t4 + 4) * 264 + cb]);
#pragma unroll
                for (int i = 0; i < 4; i++) mma_tf32(acc[i][j], af[i], b0, b1);
            }
        }
    }

#pragma unroll
    for (int i = 0; i < 4; i++) {
        int r = m0 + wm * 64 + i * 16 + g;
#pragma unroll
        for (int j = 0; j < 8; j++) {
            int c = wn * 64 + j * 8 + t4 * 2;
            float bb0 = bias[c], bb1 = bias[c + 1];
            float2 v0 = make_float2(f2tf32((acc[i][j][0] + bb0) * scl),
                                    f2tf32((acc[i][j][1] + bb1) * scl));
            float2 v1 = make_float2(f2tf32((acc[i][j][2] + bb0) * scl),
                                    f2tf32((acc[i][j][3] + bb1) * scl));
            *(float2*)(dst + (size_t)r * NIN + c) = v0;
            *(float2*)(dst + (size_t)(r + 8) * NIN + c) = v1;
        }
    }
}

// ---------------------------------------------------------------------------
// Attention: S = Q @ K^T (log2 domain). E = exp2(S) via h2exp2 (f16x2 MUFU,
// half the MUFU ops), stored fp16. rowsum over fp16 values -> g_recip.
// CTA: 128 q x 128 k, cp.async 3-stage. smem 61952 B.
// ---------------------------------------------------------------------------
__global__ __launch_bounds__(256, 2) void attn_kernel(
    const int* __restrict__ len_a, const int* __restrict__ len_b) {
    extern __shared__ float sm[];
    float* Qs = sm;             // 3*2560
    float* Ks = sm + 7680;      // 3*2560
    float* srow = sm + 15360;   // 128

    int side = blockIdx.z, batch = blockIdx.y, q0 = blockIdx.x * 128;
    int len_q = (side == 0) ? len_a[batch] : len_b[batch];
    int len_k = (side == 0) ? len_b[batch] : len_a[batch];
    if (q0 >= len_q) return;

    const float* Qg = g_proj[side == 0 ? 0 : 2] + (size_t)batch * LSEQ * NIN;
    const float* Kg = g_proj[side == 0 ? 3 : 1] + (size_t)batch * LSEQ * NIN;
    __half* Eb = g_exp + (size_t)(side * NB + batch) * LSEQ * LSEQ;

    int tid = threadIdx.x;
    int w = tid >> 5, lane = tid & 31;
    int wm = w & 1, wn = w >> 1;
    int g = lane >> 2, t4 = lane & 3;

    uint32_t smb = (uint32_t)__cvta_generic_to_shared(sm);

    int qrow[2], qcol[2];
#pragma unroll
    for (int i = 0; i < 2; i++) {
        int c = tid + 256 * i;
        qrow[i] = c >> 2;  qcol[i] = (c & 3) * 4;
    }

    if (tid < 128) srow[tid] = 0.f;

    int nkt = (len_k + 127) >> 7;
    for (int kt = 0; kt < nkt; kt++) {
        int k0 = kt * 128;
        float acc[4][4][4] = {};
        const int NS = NIN / 16;  // 16

        __syncthreads();

#pragma unroll
        for (int p = 0; p < 2; p++) {
#pragma unroll
            for (int i = 0; i < 2; i++) {
                CP16(smb + (p * 2560 + qrow[i] * 20 + qcol[i]) * 4,
                     Qg + (size_t)(q0 + qrow[i]) * NIN + p * 16 + qcol[i]);
                CP16(smb + (7680 + p * 2560 + qrow[i] * 20 + qcol[i]) * 4,
                     Kg + (size_t)(k0 + qrow[i]) * NIN + p * 16 + qcol[i]);
            }
            CP_COMMIT();
        }

        for (int s = 0; s < NS; s++) {
            if (s + 2 <= NS) { CP_WAIT(1); } else { CP_WAIT(0); }
            __syncthreads();
            if (s + 2 < NS) {
                int pb = (s + 2) % 3;
#pragma unroll
                for (int i = 0; i < 2; i++) {
                    CP16(smb + (pb * 2560 + qrow[i] * 20 + qcol[i]) * 4,
                         Qg + (size_t)(q0 + qrow[i]) * NIN + (s + 2) * 16 + qcol[i]);
                    CP16(smb + (7680 + pb * 2560 + qrow[i] * 20 + qcol[i]) * 4,
                         Kg + (size_t)(k0 + qrow[i]) * NIN + (s + 2) * 16 + qcol[i]);
                }
                CP_COMMIT();
            }
            const float* Qb = Qs + (s % 3) * 2560;
            const float* Kb = Ks + (s % 3) * 2560;
#pragma unroll
            for (int ks = 0; ks < 2; ks++) {
                int kb = ks * 8;
                uint32_t af[4][4];
#pragma unroll
                for (int i = 0; i < 4; i++) {
                    int r = wm * 64 + i * 16 + g;
                    af[i][0] = __float_as_uint(Qb[r * 20 + kb + t4]);
                    af[i][1] = __float_as_uint(Qb[(r + 8) * 20 + kb + t4]);
                    af[i][2] = __float_as_uint(Qb[r * 20 + kb + t4 + 4]);
                    af[i][3] = __float_as_uint(Qb[(r + 8) * 20 + kb + t4 + 4]);
                }
#pragma unroll
                for (int j = 0; j < 4; j++) {
                    int cb = wn * 32 + j * 8 + g;
                    uint32_t b0 = __float_as_uint(Kb[cb * 20 + kb + t4]);
                    uint32_t b1 = __float_as_uint(Kb[cb * 20 + kb + t4 + 4]);
#pragma unroll
                    for (int i = 0; i < 4; i++) mma_tf32(acc[i][j], af[i], b0, b1);
                }
            }
        }

        // epilogue: mask -> f16x2 exp2 -> fp16 store + rowsums
#pragma unroll
        for (int i = 0; i < 4; i++) {
            int r = wm * 64 + i * 16 + g;
            float rs0 = 0.f, rs1 = 0.f;
#pragma unroll
            for (int j = 0; j < 4; j++) {
                int kc = k0 + wn * 32 + j * 8 + t4 * 2;
                bool v0 = kc < len_k, v1 = kc + 1 < len_k;
                float2 p0 = make_float2(v0 ? acc[i][j][0] : -1e4f,
                                        v1 ? acc[i][j][1] : -1e4f);
                float2 p1 = make_float2(v0 ? acc[i][j][2] : -1e4f,
                                        v1 ? acc[i][j][3] : -1e4f);
                __half2 e0 = h2exp2(__float22half2_rn(p0));
                __half2 e1 = h2exp2(__float22half2_rn(p1));
                __stcs((unsigned int*)(Eb + (size_t)(q0 + r) * LSEQ + kc),
                       *(unsigned int*)&e0);
                __stcs((unsigned int*)(Eb + (size_t)(q0 + r + 8) * LSEQ + kc),
                       *(unsigned int*)&e1);
                float2 f0 = __half22float2(e0), f1 = __half22float2(e1);
                rs0 += f0.x + f0.y;
                rs1 += f1.x + f1.y;
            }
            rs0 += __shfl_xor_sync(~0u, rs0, 1); rs0 += __shfl_xor_sync(~0u, rs0, 2);
            rs1 += __shfl_xor_sync(~0u, rs1, 1); rs1 += __shfl_xor_sync(~0u, rs1, 2);
            if (t4 == 0) {
                atomicAdd(&srow[r], rs0);
                atomicAdd(&srow[r + 8], rs1);
            }
        }
    }
    __syncthreads();
    if (tid < 128)
        g_recip[(side * NB + batch) * LSEQ + q0 + tid] = 1.0f / srow[tid];
}

// colsum over fp16 E: thread owns a half2 column pair; 4-way q-split.
__global__ __launch_bounds__(128) void colsum_kernel(
    const int* __restrict__ len_a, const int* __restrict__ len_b) {
    int side = blockIdx.z, batch = blockIdx.y;
    int len_q = (side == 0) ? len_a[batch] : len_b[batch];
    int len_k = (side == 0) ? len_b[batch] : len_a[batch];
    int kc = blockIdx.x & 3, qc = blockIdx.x >> 2;
    int kp = kc * 128 + threadIdx.x;   // half2 pair index (cols 2kp, 2kp+1)
    int qlo = qc * 256;
    if (2 * kp >= len_k || qlo >= len_q) return;
    int qhi = min(qlo + 256, len_q);
    const __half2* E =
        (const __half2*)(g_exp + (size_t)(side * NB + batch) * LSEQ * LSEQ) + kp;
    const float* r = g_recip + (side * NB + batch) * LSEQ;
    float l0 = 0, h0 = 0, l1 = 0, h1 = 0, l2 = 0, h2v = 0, l3 = 0, h3 = 0;
    int q = qlo;
    for (; q + 8 <= qhi; q += 8) {
        __half2 v[8];
#pragma unroll
        for (int i = 0; i < 8; i++) v[i] = __ldcs(E + (size_t)(q + i) * (LSEQ / 2));
#pragma unroll
        for (int i = 0; i < 8; i += 4) {
            float2 f0 = __half22float2(v[i]);
            float2 f1 = __half22float2(v[i + 1]);
            float2 f2 = __half22float2(v[i + 2]);
            float2 f3 = __half22float2(v[i + 3]);
            l0 += f0.x * r[q + i];     h0 += f0.y * r[q + i];
            l1 += f1.x * r[q + i + 1]; h1 += f1.y * r[q + i + 1];
            l2 += f2.x * r[q + i + 2]; h2v += f2.y * r[q + i + 2];
            l3 += f3.x * r[q + i + 3]; h3 += f3.y * r[q + i + 3];
        }
    }
    for (; q < qhi; q++) {
        float2 f = __half22float2(__ldcs(E + (size_t)q * (LSEQ / 2)));
        l0 += f.x * r[q]; h0 += f.y * r[q];
    }
    int base = (side * NB + batch) * LSEQ + 2 * kp;
    atomicAdd(&g_colsum[base], (l0 + l1) + (l2 + l3));
    atomicAdd(&g_colsum[base + 1], (h0 + h1) + (h2v + h3));
}

// t[sb,:] += colsum_chunk @ pad.  8-way k split, unroll 8.
__global__ __launch_bounds__(640) void tvec_kernel(
    const float* __restrict__ a_pad, const float* __restrict__ b_pad,
    const int* __restrict__ len_a, const int* __restrict__ len_b) {
    int sb = blockIdx.y, side = sb >> 6, batch = sb & 63;
    int lk = (side == 0) ? len_b[batch] : len_a[batch];
    int k0 = blockIdx.x * 128;
    if (k0 >= lk) return;
    int k1 = min(k0 + 128, lk);
    const float* pad = ((side == 0) ? b_pad : a_pad) + (size_t)batch * LSEQ * DIMK;
    const float* cs = g_colsum + sb * LSEQ;
    int d = threadIdx.x;
    float a0 = 0.f, a1 = 0.f, a2 = 0.f, a3 = 0.f;
    int k = k0;
    for (; k + 8 <= k1; k += 8) {
        float v[8];
#pragma unroll
        for (int i = 0; i < 8; i++) v[i] = __ldcs(pad + (size_t)(k + i) * DIMK + d);
        a0 += cs[k] * v[0] + cs[k + 4] * v[4];
        a1 += cs[k + 1] * v[1] + cs[k + 5] * v[5];
        a2 += cs[k + 2] * v[2] + cs[k + 6] * v[6];
        a3 += cs[k + 3] * v[3] + cs[k + 7] * v[7];
    }
    for (; k < k1; k++) a0 += cs[k] * __ldcs(pad + (size_t)k * DIMK + d);
    atomicAdd(&g_t[sb * DIMK + d], (a0 + a1) + (a2 + a3));
}

// out[128,1024] = diag(1/len) * (t[128,640] @ Wv[640,1024]) + bv.
__global__ __launch_bounds__(256) void emb_kernel(
    const float* __restrict__ Wv, const float* __restrict__ bv,
    const int* __restrict__ len_a, const int* __restrict__ len_b,
    float* __restrict__ out) {
    __shared__ float ts[16][DIMK];
    int r0 = blockIdx.y * 16;
    int o = blockIdx.x * 256 + threadIdx.x;
    for (int i = threadIdx.x; i < 16 * DIMK; i += 256)
        ts[i / DIMK][i % DIMK] = g_t[(size_t)r0 * DIMK + i];
    __syncthreads();
    float acc[16] = {};
    for (int d = 0; d < DIMK; d++) {
        float wv = Wv[(size_t)d * NOUT + o];
#pragma unroll
        for (int r = 0; r < 16; r++) acc[r] += ts[r][d] * wv;
    }
    float bb = bv[o];
#pragma unroll
    for (int r = 0; r < 16; r++) {
        int sb = r0 + r;
        int side = sb >> 6, batch = sb & 63;
        float inv = 1.0f / (float)((side == 0 ? len_a : len_b)[batch]);
        out[(size_t)sb * NOUT + o] = acc[r] * inv + bb;
    }
}

extern "C" void kernel_launch(void* const* d_in, const int* in_sizes, int n_in,
                              void* d_out, int out_size) {
    const float* a_pad = (const float*)d_in[0];
    const float* b_pad = (const float*)d_in[1];
    const int*   len_a = (const int*)d_in[2];
    const int*   len_b = (const int*)d_in[3];
    const float* Wq = (const float*)d_in[4];
    const float* bq = (const float*)d_in[5];
    const float* Wk = (const float*)d_in[6];
    const float* bk = (const float*)d_in[7];
    const float* Wv = (const float*)d_in[8];
    const float* bv = (const float*)d_in[9];
    float* out = (float*)d_out;

    cudaFuncSetAttribute(proj_kernel, cudaFuncAttributeMaxDynamicSharedMemorySize, 81408);
    cudaFuncSetAttribute(attn_kernel, cudaFuncAttributeMaxDynamicSharedMemorySize, 61952);

    init_kernel<<<512, 256>>>();                                   // launch 0
    dummy_kernel<<<1, 32>>>();                                     // launch 1 (capture shim)
    dim3 gp(NB * LSEQ / 128, 1, 4);
    proj_kernel<<<gp, 256, 81408>>>(a_pad, b_pad, Wq, bq, Wk, bk, len_a, len_b);  // 2
    dim3 ga(LSEQ / 128, NB, 2);
    attn_kernel<<<ga, 256, 61952>>>(len_a, len_b);                 // launch 3 -> profiled
    dim3 gc(16, NB, 2);
    colsum_kernel<<<gc, 128>>>(len_a, len_b);
    dim3 gt(8, 2 * NB);
    tvec_kernel<<<gt, 640>>>(a_pad, b_pad, len_a, len_b);
    dim3 ge(4, 8);
    emb_kernel<<<ge, 256>>>(Wv, bv, len_a, len_b, out);
}

// round 10
// speedup vs baseline: 1.2013x; 1.1700x over previous
#include <cuda_runtime.h>
#include <cuda_fp16.h>
#include <cstdint>

#define NB   64
#define LSEQ 1024
#define DIMK 640
#define NIN  256
#define NOUT 1024

// scratch: 0=Qa(log2e-scaled,fp16), 1=Ka(fp16), 2=Qb, 3=Kb
__device__ __half g_proj[4][NB * LSEQ * NIN];          // 128 MB
__device__ __half g_exp[2ull * NB * LSEQ * LSEQ];      // 256 MB
__device__ float  g_recip[2 * NB * LSEQ];
__device__ float  g_colsum[2 * NB * LSEQ];
__device__ float  g_t[2 * NB * DIMK];

__device__ __forceinline__ void mma_tf32(float c[4], const uint32_t a[4],
                                         uint32_t b0, uint32_t b1) {
    asm volatile(
        "mma.sync.aligned.m16n8k8.row.col.f32.tf32.tf32.f32 "
        "{%0,%1,%2,%3}, {%4,%5,%6,%7}, {%8,%9}, {%0,%1,%2,%3};"
        : "+f"(c[0]), "+f"(c[1]), "+f"(c[2]), "+f"(c[3])
        : "r"(a[0]), "r"(a[1]), "r"(a[2]), "r"(a[3]), "r"(b0), "r"(b1));
}

__device__ __forceinline__ void mma_f16(float c[4], const uint32_t a[4],
                                        uint32_t b0, uint32_t b1) {
    asm volatile(
        "mma.sync.aligned.m16n8k16.row.col.f32.f16.f16.f32 "
        "{%0,%1,%2,%3}, {%4,%5,%6,%7}, {%8,%9}, {%0,%1,%2,%3};"
        : "+f"(c[0]), "+f"(c[1]), "+f"(c[2]), "+f"(c[3])
        : "r"(a[0]), "r"(a[1]), "r"(a[2]), "r"(a[3]), "r"(b0), "r"(b1));
}

#define CP16(dst_u32, src_ptr) \
    asm volatile("cp.async.cg.shared.global [%0], [%1], 16;" :: "r"(dst_u32), "l"(src_ptr))
#define CP_COMMIT() asm volatile("cp.async.commit_group;")
#define CP_WAIT(n)  asm volatile("cp.async.wait_group %0;" :: "n"(n))

__global__ __launch_bounds__(256) void init_kernel() {
    int i = blockIdx.x * 256 + threadIdx.x;
    if (i < 2 * NB * LSEQ) g_colsum[i] = 0.f;
    if (i < 2 * NB * DIMK) g_t[i] = 0.f;
}

// no-op: keeps attn_kernel in the ncu capture slot (launch idx 3)
__global__ void dummy_kernel() {}

// ---------------------------------------------------------------------------
// Projection: C[65536,256] = X[65536,640] @ W[640,256].
// tf32 mainloop (unchanged); epilogue stores fp16 (10-bit mantissa == tf32).
// Q-side scale includes log2(e) so scores land in log2 domain.
// ---------------------------------------------------------------------------
__global__ __launch_bounds__(256) void proj_kernel(
    const float* __restrict__ a_pad, const float* __restrict__ b_pad,
    const float* __restrict__ Wq, const float* __restrict__ bq,
    const float* __restrict__ Wk, const float* __restrict__ bk,
    const int* __restrict__ len_a, const int* __restrict__ len_b) {
    extern __shared__ float sm[];
    float* As = sm;          // 3*2560
    float* Bs = sm + 7680;   // 3*4224

    int z = blockIdx.z;
    int m0 = blockIdx.x * 128;
    int batch = m0 >> 10, local = m0 & 1023;
    int len = ((z < 2) ? len_a : len_b)[batch];
    if (local >= len) return;

    const float* X    = (z < 2) ? a_pad : b_pad;
    const float* W    = (z & 1) ? Wk : Wq;
    const float* bias = (z & 1) ? bk : bq;
    float scl         = (z & 1) ? 1.0f : 0.09016844005f;  // log2(e)/16
    __half* dst       = g_proj[z];

    int tid = threadIdx.x;
    int w = tid >> 5, lane = tid & 31;
    int wm = w & 1, wn = w >> 1;
    int g = lane >> 2, t4 = lane & 3;

    uint32_t smb = (uint32_t)__cvta_generic_to_shared(sm);

    int ar[2], ac[2], br[4], bc[4];
#pragma unroll
    for (int i = 0; i < 2; i++) {
        int idx = tid + 256 * i;
        ar[i] = idx >> 2;  ac[i] = (idx & 3) * 4;
    }
#pragma unroll
    for (int i = 0; i < 4; i++) {
        int idx = tid + 256 * i;
        br[i] = idx >> 6;  bc[i] = (idx & 63) * 4;
    }

    float acc[4][8][4] = {};
    const int NS = DIMK / 16;  // 40

#pragma unroll
    for (int p = 0; p < 2; p++) {
#pragma unroll
        for (int i = 0; i < 2; i++)
            CP16(smb + (p * 2560 + ar[i] * 20 + ac[i]) * 4,
                 X + (size_t)(m0 + ar[i]) * DIMK + p * 16 + ac[i]);
#pragma unroll
        for (int i = 0; i < 4; i++)
            CP16(smb + (7680 + p * 4224 + br[i] * 264 + bc[i]) * 4,
                 W + (size_t)(p * 16 + br[i]) * NIN + bc[i]);
        CP_COMMIT();
    }

    for (int s = 0; s < NS; s++) {
        if (s + 2 <= NS) { CP_WAIT(1); } else { CP_WAIT(0); }
        __syncthreads();
        if (s + 2 < NS) {
            int pb = (s + 2) % 3;
#pragma unroll
            for (int i = 0; i < 2; i++)
                CP16(smb + (pb * 2560 + ar[i] * 20 + ac[i]) * 4,
                     X + (size_t)(m0 + ar[i]) * DIMK + (s + 2) * 16 + ac[i]);
#pragma unroll
            for (int i = 0; i < 4; i++)
                CP16(smb + (7680 + pb * 4224 + br[i] * 264 + bc[i]) * 4,
                     W + (size_t)((s + 2) * 16 + br[i]) * NIN + bc[i]);
            CP_COMMIT();
        }
        const float* Ab = As + (s % 3) * 2560;
        const float* Bb = Bs + (s % 3) * 4224;
#pragma unroll
        for (int ks = 0; ks < 2; ks++) {
            int kb = ks * 8;
            uint32_t af[4][4];
#pragma unroll
            for (int i = 0; i < 4; i++) {
                int r = wm * 64 + i * 16 + g;
                af[i][0] = __float_as_uint(Ab[r * 20 + kb + t4]);
                af[i][1] = __float_as_uint(Ab[(r + 8) * 20 + kb + t4]);
                af[i][2] = __float_as_uint(Ab[r * 20 + kb + t4 + 4]);
                af[i][3] = __float_as_uint(Ab[(r + 8) * 20 + kb + t4 + 4]);
            }
#pragma unroll
            for (int j = 0; j < 8; j++) {
                int cb = wn * 64 + j * 8 + g;
                uint32_t b0 = __float_as_uint(Bb[(kb + t4) * 264 + cb]);
                uint32_t b1 = __float_as_uint(Bb[(kb + t4 + 4) * 264 + cb]);
#pragma unroll
                for (int i = 0; i < 4; i++) mma_tf32(acc[i][j], af[i], b0, b1);
            }
        }
    }

    // epilogue: (acc+bias)*scl -> fp16 (RNA)
#pragma unroll
    for (int i = 0; i < 4; i++) {
        int r = m0 + wm * 64 + i * 16 + g;
#pragma unroll
        for (int j = 0; j < 8; j++) {
            int c = wn * 64 + j * 8 + t4 * 2;
            float bb0 = bias[c], bb1 = bias[c + 1];
            __half2 v0 = __floats2half2_rn((acc[i][j][0] + bb0) * scl,
                                           (acc[i][j][1] + bb1) * scl);
            __half2 v1 = __floats2half2_rn((acc[i][j][2] + bb0) * scl,
                                           (acc[i][j][3] + bb1) * scl);
            *(__half2*)(dst + (size_t)r * NIN + c) = v0;
            *(__half2*)(dst + (size_t)(r + 8) * NIN + c) = v1;
        }
    }
}

// ---------------------------------------------------------------------------
// Attention: S = Q @ K^T (log2 domain) with fp16 mma m16n8k16.
// CTA 128 q x 128 k, warp 64x32, 2 CTAs/SM. cp.async 3-stage, dim-chunk 32.
// smem halfs: Q 3*128*40 + K 3*128*40, + srow 128 floats = 61952 B.
// E = exp2(S) via h2exp2, stored fp16; rowsum -> g_recip.
// ---------------------------------------------------------------------------
__global__ __launch_bounds__(256, 2) void attn_kernel(
    const int* __restrict__ len_a, const int* __restrict__ len_b) {
    extern __shared__ __half smh[];
    __half* Qs = smh;              // 3 stages * 5120 halfs
    __half* Ks = smh + 15360;      // 3 stages * 5120 halfs
    float* srow = (float*)(smh + 30720);  // 128 floats

    int side = blockIdx.z, batch = blockIdx.y, q0 = blockIdx.x * 128;
    int len_q = (side == 0) ? len_a[batch] : len_b[batch];
    int len_k = (side == 0) ? len_b[batch] : len_a[batch];
    if (q0 >= len_q) return;

    const __half* Qg = g_proj[side == 0 ? 0 : 2] + (size_t)batch * LSEQ * NIN;
    const __half* Kg = g_proj[side == 0 ? 3 : 1] + (size_t)batch * LSEQ * NIN;
    __half* Eb = g_exp + (size_t)(side * NB + batch) * LSEQ * LSEQ;

    int tid = threadIdx.x;
    int w = tid >> 5, lane = tid & 31;
    int wm = w & 1, wn = w >> 1;
    int g = lane >> 2, t4 = lane & 3;

    uint32_t smb = (uint32_t)__cvta_generic_to_shared(smh);

    // 16B chunk coords: per stage per tile 128 rows x 64B -> 2 chunks/thread
    int crow[2], ccol[2];
#pragma unroll
    for (int i = 0; i < 2; i++) {
        int c = tid + 256 * i;
        crow[i] = c >> 2;  ccol[i] = (c & 3) * 8;   // halfs
    }

    if (tid < 128) srow[tid] = 0.f;

    int nkt = (len_k + 127) >> 7;
    for (int kt = 0; kt < nkt; kt++) {
        int k0 = kt * 128;
        float acc[4][4][4] = {};
        const int NS = NIN / 32;  // 8 stages of 32 dims

        __syncthreads();  // smem reuse fence (covers srow init on kt==0)

#pragma unroll
        for (int p = 0; p < 2; p++) {
#pragma unroll
            for (int i = 0; i < 2; i++) {
                CP16(smb + (p * 5120 + crow[i] * 40 + ccol[i]) * 2,
                     Qg + (size_t)(q0 + crow[i]) * NIN + p * 32 + ccol[i]);
                CP16(smb + 30720 + (p * 5120 + crow[i] * 40 + ccol[i]) * 2,
                     Kg + (size_t)(k0 + crow[i]) * NIN + p * 32 + ccol[i]);
            }
            CP_COMMIT();
        }

        for (int s = 0; s < NS; s++) {
            if (s + 2 <= NS) { CP_WAIT(1); } else { CP_WAIT(0); }
            __syncthreads();
            if (s + 2 < NS) {
                int pb = (s + 2) % 3;
#pragma unroll
                for (int i = 0; i < 2; i++) {
                    CP16(smb + (pb * 5120 + crow[i] * 40 + ccol[i]) * 2,
                         Qg + (size_t)(q0 + crow[i]) * NIN + (s + 2) * 32 + ccol[i]);
                    CP16(smb + 30720 + (pb * 5120 + crow[i] * 40 + ccol[i]) * 2,
                         Kg + (size_t)(k0 + crow[i]) * NIN + (s + 2) * 32 + ccol[i]);
                }
                CP_COMMIT();
            }
            const __half* Qb = Qs + (s % 3) * 5120;
            const __half* Kb = Ks + (s % 3) * 5120;
#pragma unroll
            for (int ks = 0; ks < 2; ks++) {     // two k16 steps per stage
                int kb = ks * 16 + t4 * 2;
                uint32_t af[4][4];
#pragma unroll
                for (int i = 0; i < 4; i++) {
                    int r = wm * 64 + i * 16 + g;
                    af[i][0] = *(const uint32_t*)(Qb + r * 40 + kb);
                    af[i][1] = *(const uint32_t*)(Qb + (r + 8) * 40 + kb);
                    af[i][2] = *(const uint32_t*)(Qb + r * 40 + kb + 8);
                    af[i][3] = *(const uint32_t*)(Qb + (r + 8) * 40 + kb + 8);
                }
#pragma unroll
                for (int j = 0; j < 4; j++) {
                    int cb = wn * 32 + j * 8 + g;
                    uint32_t b0 = *(const uint32_t*)(Kb + cb * 40 + kb);
                    uint32_t b1 = *(const uint32_t*)(Kb + cb * 40 + kb + 8);
#pragma unroll
                    for (int i = 0; i < 4; i++) mma_f16(acc[i][j], af[i], b0, b1);
                }
            }
        }

        // epilogue: mask -> f16x2 exp2 -> fp16 store + rowsums
#pragma unroll
        for (int i = 0; i < 4; i++) {
            int r = wm * 64 + i * 16 + g;
            float rs0 = 0.f, rs1 = 0.f;
#pragma unroll
            for (int j = 0; j < 4; j++) {
                int kc = k0 + wn * 32 + j * 8 + t4 * 2;
                bool v0 = kc < len_k, v1 = kc + 1 < len_k;
                float2 p0 = make_float2(v0 ? acc[i][j][0] : -1e4f,
                                        v1 ? acc[i][j][1] : -1e4f);
                float2 p1 = make_float2(v0 ? acc[i][j][2] : -1e4f,
                                        v1 ? acc[i][j][3] : -1e4f);
                __half2 e0 = h2exp2(__float22half2_rn(p0));
                __half2 e1 = h2exp2(__float22half2_rn(p1));
                __stcs((unsigned int*)(Eb + (size_t)(q0 + r) * LSEQ + kc),
                       *(unsigned int*)&e0);
                __stcs((unsigned int*)(Eb + (size_t)(q0 + r + 8) * LSEQ + kc),
                       *(unsigned int*)&e1);
                float2 f0 = __half22float2(e0), f1 = __half22float2(e1);
                rs0 += f0.x + f0.y;
                rs1 += f1.x + f1.y;
            }
            rs0 += __shfl_xor_sync(~0u, rs0, 1); rs0 += __shfl_xor_sync(~0u, rs0, 2);
            rs1 += __shfl_xor_sync(~0u, rs1, 1); rs1 += __shfl_xor_sync(~0u, rs1, 2);
            if (t4 == 0) {
                atomicAdd(&srow[r], rs0);
                atomicAdd(&srow[r + 8], rs1);
            }
        }
    }
    __syncthreads();
    if (tid < 128)
        g_recip[(side * NB + batch) * LSEQ + q0 + tid] = 1.0f / srow[tid];
}

// colsum over fp16 E: thread owns a half2 column pair; 4-way q-split.
__global__ __launch_bounds__(128) void colsum_kernel(
    const int* __restrict__ len_a, const int* __restrict__ len_b) {
    int side = blockIdx.z, batch = blockIdx.y;
    int len_q = (side == 0) ? len_a[batch] : len_b[batch];
    int len_k = (side == 0) ? len_b[batch] : len_a[batch];
    int kc = blockIdx.x & 3, qc = blockIdx.x >> 2;
    int kp = kc * 128 + threadIdx.x;
    int qlo = qc * 256;
    if (2 * kp >= len_k || qlo >= len_q) return;
    int qhi = min(qlo + 256, len_q);
    const __half2* E =
        (const __half2*)(g_exp + (size_t)(side * NB + batch) * LSEQ * LSEQ) + kp;
    const float* r = g_recip + (side * NB + batch) * LSEQ;
    float l0 = 0, h0 = 0, l1 = 0, h1 = 0, l2 = 0, h2v = 0, l3 = 0, h3 = 0;
    int q = qlo;
    for (; q + 8 <= qhi; q += 8) {
        __half2 v[8];
#pragma unroll
        for (int i = 0; i < 8; i++) v[i] = __ldcs(E + (size_t)(q + i) * (LSEQ / 2));
#pragma unroll
        for (int i = 0; i < 8; i += 4) {
            float2 f0 = __half22float2(v[i]);
            float2 f1 = __half22float2(v[i + 1]);
            float2 f2 = __half22float2(v[i + 2]);
            float2 f3 = __half22float2(v[i + 3]);
            l0 += f0.x * r[q + i];     h0 += f0.y * r[q + i];
            l1 += f1.x * r[q + i + 1]; h1 += f1.y * r[q + i + 1];
            l2 += f2.x * r[q + i + 2]; h2v += f2.y * r[q + i + 2];
            l3 += f3.x * r[q + i + 3]; h3 += f3.y * r[q + i + 3];
        }
    }
    for (; q < qhi; q++) {
        float2 f = __half22float2(__ldcs(E + (size_t)q * (LSEQ / 2)));
        l0 += f.x * r[q]; h0 += f.y * r[q];
    }
    int base = (side * NB + batch) * LSEQ + 2 * kp;
    atomicAdd(&g_colsum[base], (l0 + l1) + (l2 + l3));
    atomicAdd(&g_colsum[base + 1], (h0 + h1) + (h2v + h3));
}

// t[sb,:] += colsum_chunk @ pad.  8-way k split, unroll 8.
__global__ __launch_bounds__(640) void tvec_kernel(
    const float* __restrict__ a_pad, const float* __restrict__ b_pad,
    const int* __restrict__ len_a, const int* __restrict__ len_b) {
    int sb = blockIdx.y, side = sb >> 6, batch = sb & 63;
    int lk = (side == 0) ? len_b[batch] : len_a[batch];
    int k0 = blockIdx.x * 128;
    if (k0 >= lk) return;
    int k1 = min(k0 + 128, lk);
    const float* pad = ((side == 0) ? b_pad : a_pad) + (size_t)batch * LSEQ * DIMK;
    const float* cs = g_colsum + sb * LSEQ;
    int d = threadIdx.x;
    float a0 = 0.f, a1 = 0.f, a2 = 0.f, a3 = 0.f;
    int k = k0;
    for (; k + 8 <= k1; k += 8) {
        float v[8];
#pragma unroll
        for (int i = 0; i < 8; i++) v[i] = __ldcs(pad + (size_t)(k + i) * DIMK + d);
        a0 += cs[k] * v[0] + cs[k + 4] * v[4];
        a1 += cs[k + 1] * v[1] + cs[k + 5] * v[5];
        a2 += cs[k + 2] * v[2] + cs[k + 6] * v[6];
        a3 += cs[k + 3] * v[3] + cs[k + 7] * v[7];
    }
    for (; k < k1; k++) a0 += cs[k] * __ldcs(pad + (size_t)k * DIMK + d);
    atomicAdd(&g_t[sb * DIMK + d], (a0 + a1) + (a2 + a3));
}

// out[128,1024] = diag(1/len) * (t[128,640] @ Wv[640,1024]) + bv.
__global__ __launch_bounds__(256) void emb_kernel(
    const float* __restrict__ Wv, const float* __restrict__ bv,
    const int* __restrict__ len_a, const int* __restrict__ len_b,
    float* __restrict__ out) {
    __shared__ float ts[16][DIMK];
    int r0 = blockIdx.y * 16;
    int o = blockIdx.x * 256 + threadIdx.x;
    for (int i = threadIdx.x; i < 16 * DIMK; i += 256)
        ts[i / DIMK][i % DIMK] = g_t[(size_t)r0 * DIMK + i];
    __syncthreads();
    float acc[16] = {};
    for (int d = 0; d < DIMK; d++) {
        float wv = Wv[(size_t)d * NOUT + o];
#pragma unroll
        for (int r = 0; r < 16; r++) acc[r] += ts[r][d] * wv;
    }
    float bb = bv[o];
#pragma unroll
    for (int r = 0; r < 16; r++) {
        int sb = r0 + r;
        int side = sb >> 6, batch = sb & 63;
        float inv = 1.0f / (float)((side == 0 ? len_a : len_b)[batch]);
        out[(size_t)sb * NOUT + o] = acc[r] * inv + bb;
    }
}

extern "C" void kernel_launch(void* const* d_in, const int* in_sizes, int n_in,
                              void* d_out, int out_size) {
    const float* a_pad = (const float*)d_in[0];
    const float* b_pad = (const float*)d_in[1];
    const int*   len_a = (const int*)d_in[2];
    const int*   len_b = (const int*)d_in[3];
    const float* Wq = (const float*)d_in[4];
    const float* bq = (const float*)d_in[5];
    const float* Wk = (const float*)d_in[6];
    const float* bk = (const float*)d_in[7];
    const float* Wv = (const float*)d_in[8];
    const float* bv = (const float*)d_in[9];
    float* out = (float*)d_out;

    cudaFuncSetAttribute(proj_kernel, cudaFuncAttributeMaxDynamicSharedMemorySize, 81408);
    cudaFuncSetAttribute(attn_kernel, cudaFuncAttributeMaxDynamicSharedMemorySize, 61952);

    init_kernel<<<512, 256>>>();                                   // launch 0
    dummy_kernel<<<1, 32>>>();                                     // launch 1 (capture shim)
    dim3 gp(NB * LSEQ / 128, 1, 4);
    proj_kernel<<<gp, 256, 81408>>>(a_pad, b_pad, Wq, bq, Wk, bk, len_a, len_b);  // 2
    dim3 ga(LSEQ / 128, NB, 2);
    attn_kernel<<<ga, 256, 61952>>>(len_a, len_b);                 // launch 3 -> profiled
    dim3 gc(16, NB, 2);
    colsum_kernel<<<gc, 128>>>(len_a, len_b);
    dim3 gt(8, 2 * NB);
    tvec_kernel<<<gt, 640>>>(a_pad, b_pad, len_a, len_b);
    dim3 ge(4, 8);
    emb_kernel<<<ge, 256>>>(Wv, bv, len_a, len_b, out);
}